// round 4
// baseline (speedup 1.0000x reference)
#include <cuda_runtime.h>

#define E     1024
#define LAY   24
#define HID   4096
#define VOCAB 50277
#define NBLK  148
#define NTHR  384
#define NWARP (NTHR / 32)          // 12
#define GWARPS (NBLK * NWARP)      // 1776

// ---------------- scratch (device globals: no allocations allowed) ----------
__device__ __align__(16) float g_x[E];
__device__ __align__(16) float g_r[E];
__device__ __align__(16) float g_k[E];
__device__ __align__(16) float g_v[E];
__device__ __align__(16) float g_rf[E];
__device__ __align__(16) float g_kf[HID];
__device__ unsigned g_bar_leaf[8] = {0,0,0,0,0,0,0,0};
__device__ unsigned g_bar_root = 0;
__device__ volatile unsigned g_bar_gen = 0;

struct Params {
    const int*   ctx;
    const float *xx_att, *aa_att, *bb_att, *pp_att, *xx_ffn;
    const float *emb_w, *head_w;
    const float *ln0_w, *ln0_b, *ln1_w, *ln1_b, *ln2_w, *ln2_b, *lno_w, *lno_b;
    const float *mk, *mv, *mr, *tf, *td;
    const float *Wr, *Wk, *Wv, *Wo;
    const float *fmk, *fmr, *Fr, *Fk, *Fv;
    float* out;
};

// ------------- two-level software grid barrier (8 leaf buckets + root) ------
__device__ __forceinline__ void grid_sync() {
    __syncthreads();
    if (threadIdx.x == 0) {
        const unsigned gen = g_bar_gen;
        const int b = blockIdx.x & 7;
        const unsigned cnt = 18u + (b < 4 ? 1u : 0u);   // 148 = 4*19 + 4*18
        __threadfence();
        if (atomicAdd(&g_bar_leaf[b], 1u) == cnt - 1u) {
            atomicExch(&g_bar_leaf[b], 0u);
            if (atomicAdd(&g_bar_root, 1u) == 7u) {
                atomicExch(&g_bar_root, 0u);
                __threadfence();
                g_bar_gen = gen + 1u;
            } else {
                while (g_bar_gen == gen) { __nanosleep(32); }
            }
        } else {
            while (g_bar_gen == gen) { __nanosleep(32); }
        }
        __threadfence();
    }
    __syncthreads();
}

// named barrier among a subset of warps (id 1..15, cnt multiple of 32)
__device__ __forceinline__ void barn(int id, int cnt) {
    asm volatile("bar.sync %0, %1;" :: "r"(id), "r"(cnt) : "memory");
}

// ---------------- block reduction (sum, broadcast) ---------------------------
__device__ __forceinline__ float block_sum(float v, float* red) {
    #pragma unroll
    for (int o = 16; o; o >>= 1) v += __shfl_xor_sync(0xffffffffu, v, o);
    int w = threadIdx.x >> 5;
    if ((threadIdx.x & 31) == 0) red[w] = v;
    __syncthreads();
    if (threadIdx.x < 32) {
        float t = (threadIdx.x < NWARP) ? red[threadIdx.x] : 0.f;
        #pragma unroll
        for (int o = 16; o; o >>= 1) t += __shfl_xor_sync(0xffffffffu, t, o);
        if (threadIdx.x == 0) red[0] = t;
    }
    __syncthreads();
    float r = red[0];
    __syncthreads();
    return r;
}

// two-pass LayerNorm: src (global) -> dst (shared), per-block redundant
__device__ void block_ln(const float* __restrict__ src,
                         const float* __restrict__ w,
                         const float* __restrict__ b,
                         float* dst, float* red) {
    float s = 0.f;
    for (int j = threadIdx.x; j < E; j += NTHR) { float t = src[j]; dst[j] = t; s += t; }
    float mean = block_sum(s, red) * (1.f / E);
    float s2 = 0.f;
    for (int j = threadIdx.x; j < E; j += NTHR) { float c = dst[j] - mean; s2 += c * c; }
    float inv = rsqrtf(block_sum(s2, red) * (1.f / E) + 1e-5f);
    for (int j = threadIdx.x; j < E; j += NTHR)
        dst[j] = (dst[j] - mean) * inv * w[j] + b[j];
    __syncthreads();
}

// ---------------- GEMV pieces ------------------------------------------------
__device__ __forceinline__ float red32(float s) {
    #pragma unroll
    for (int o = 16; o; o >>= 1) s += __shfl_xor_sync(0xffffffffu, s, o);
    return s;
}

// 8x LDG.128 = one 1024-float row segment into registers
__device__ __forceinline__ void pf8(const float* __restrict__ Wrow, int lane,
                                    float4 (&a)[8]) {
    const float4* W = (const float4*)Wrow;
    #pragma unroll
    for (int t = 0; t < 8; t++) a[t] = W[lane + 32 * t];
}
// 4x LDG.128 = one 512-float half-row
__device__ __forceinline__ void pf4(const float* __restrict__ Whalf, int lane,
                                    float4 (&a)[4]) {
    const float4* W = (const float4*)Whalf;
    #pragma unroll
    for (int t = 0; t < 4; t++) a[t] = W[lane + 32 * t];
}

__device__ __forceinline__ float dot8_pf(const float4 (&a)[8],
                                         const float* __restrict__ vec, int lane) {
    const float4* v = (const float4*)vec;
    float s = 0.f;
    #pragma unroll
    for (int t = 0; t < 8; t++) {
        float4 x = v[lane + 32 * t];
        s = fmaf(a[t].x, x.x, s); s = fmaf(a[t].y, x.y, s);
        s = fmaf(a[t].z, x.z, s); s = fmaf(a[t].w, x.w, s);
    }
    return red32(s);
}
__device__ __forceinline__ float dot4_pf(const float4 (&a)[4],
                                         const float* __restrict__ vec, int lane) {
    const float4* v = (const float4*)vec;
    float s = 0.f;
    #pragma unroll
    for (int t = 0; t < 4; t++) {
        float4 x = v[lane + 32 * t];
        s = fmaf(a[t].x, x.x, s); s = fmaf(a[t].y, x.y, s);
        s = fmaf(a[t].z, x.z, s); s = fmaf(a[t].w, x.w, s);
    }
    return red32(s);
}

__device__ __forceinline__ float sigmoidf_(float x) {
    return 1.f / (1.f + expf(-x));
}

// phase-A row -> weight pointer (rows 0..1023:Wr, 1024..2047:Wk, 2048..3071:Wv)
__device__ __forceinline__ const float* wrowA(const Params& p, int l, int row) {
    int m = row >> 10, i = row & (E - 1);
    const float* Wb = (m == 0) ? p.Wr : (m == 1) ? p.Wk : p.Wv;
    return Wb + (size_t)l * E * E + (size_t)i * E;
}

// ---------------- the whole network in one persistent kernel ----------------
__global__ void __launch_bounds__(NTHR, 1) rwkv_kernel(Params p) {
    __shared__ __align__(16) float sh[HID];   // 16KB, aliased per phase
    __shared__ float red[NWARP];
    __shared__ float psum[2 * NWARP];         // phase-B pair partials (2 banks)
    __shared__ float psd[3 * NWARP];          // phase-D group partials (3 banks)

    const int tid  = threadIdx.x;
    const int wid  = tid >> 5;
    const int gw   = blockIdx.x * NWARP + wid;
    const int lane = tid & 31;

    float* outv  = p.out;                 // logits [V]
    float* o_xx  = p.out + VOCAB;         // xx_att_r [L,E]
    float* o_aa  = o_xx  + LAY * E;
    float* o_bb  = o_aa  + LAY * E;
    float* o_pp  = o_bb  + LAY * E;
    float* o_xxf = o_pp  + LAY * E;
    float* o_da  = o_xxf + LAY * E;       // r_pre
    float* o_db  = o_da  + LAY * E;       // sigmoid(r_pre)

    float4 a[8], b[8];                    // cross-barrier prefetch buffers

    // ---- init: x0 = LN(emb[ctx], ln0) ----
    {
        int tok = p.ctx[0];
        block_ln(p.emb_w + (size_t)tok * E, p.ln0_w, p.ln0_b, sh, red);
        if (blockIdx.x == 0)
            for (int j = tid; j < E; j += NTHR) g_x[j] = sh[j];
    }
    const bool actA2 = (gw < 3 * E - GWARPS);     // gw < 1296
    pf8(wrowA(p, 0, gw), lane, a);
    if (actA2) pf8(wrowA(p, 0, gw + GWARPS), lane, b);
    grid_sync();

    for (int l = 0; l < LAY; l++) {
        const size_t lE  = (size_t)l * E;
        const size_t lEE = (size_t)l * E * E;
        const size_t lHE = (size_t)l * HID * E;
        const size_t lEH = (size_t)l * E * HID;

        // ========== Phase A: LN1 + mixes + r/k/v GEMVs (full rows) =========
        float* xn = sh; float* xk = sh + E; float* xv = sh + 2 * E; float* xr = sh + 3 * E;
        block_ln(g_x, p.ln1_w + lE, p.ln1_b + lE, xn, red);
        for (int j = tid; j < E; j += NTHR) {
            float xnj = xn[j], sx = p.xx_att[lE + j];
            float ak = p.mk[lE + j], bv = p.mv[lE + j], cr = p.mr[lE + j];
            xk[j] = xnj * ak + sx * (1.f - ak);
            xv[j] = xnj * bv + sx * (1.f - bv);
            xr[j] = xnj * cr + sx * (1.f - cr);
            if (blockIdx.x == 0) o_xx[lE + j] = xnj;
        }
        __syncthreads();
        {
            int m = gw >> 10, i = gw & (E - 1);
            const float* vec = (m == 0) ? xr : (m == 1) ? xk : xv;
            float s = dot8_pf(a, vec, lane);
            if (lane == 0) ((m == 0) ? g_r : (m == 1) ? g_k : g_v)[i] = s;
        }
        if (actA2) {
            int row = gw + GWARPS;
            int m = row >> 10, i = row & (E - 1);
            const float* vec = (m == 0) ? xr : (m == 1) ? xk : xv;
            float s = dot8_pf(b, vec, lane);
            if (lane == 0) ((m == 0) ? g_r : (m == 1) ? g_k : g_v)[i] = s;
        }
        // prefetch phase-B half-rows (it0: all warps; it1: gw<272)
        const int  rowB  = gw >> 1, halfB = gw & 1;
        const bool actB2 = (gw < 2 * E - GWARPS);   // gw < 272
        pf4(p.Wo + lEE + (size_t)rowB * E + halfB * (E / 2), lane,
            *(float4(*)[4])&a[0]);
        if (actB2)
            pf4(p.Wo + lEE + (size_t)(rowB + GWARPS / 2) * E + halfB * (E / 2), lane,
                *(float4(*)[4])&a[4]);
        grid_sync();

        // ========== Phase B: WKV elementwise + Wo GEMV (half rows) =========
        float* oin = sh;
        for (int j = tid; j < E; j += NTHR) {
            float kj = g_k[j], vj = g_v[j], rp = g_r[j];
            float aa = p.aa_att[lE + j], bb = p.bb_att[lE + j], pp = p.pp_att[lE + j];
            float tf = p.tf[lE + j],     td = p.td[lE + j];
            float ww = tf + kj;
            float q  = fmaxf(pp, ww);
            float e1 = expf(pp - q), e2 = expf(ww - q);
            float av = e1 * aa + e2 * vj;
            float bv = e1 * bb + e2;
            float rr = sigmoidf_(rp);
            oin[j] = rr * av / bv;
            if (blockIdx.x == 0) {
                float ww2 = pp + td;
                float q2  = fmaxf(ww2, kj);
                float f1  = expf(ww2 - q2), f2 = expf(kj - q2);
                o_aa[lE + j] = f1 * aa + f2 * vj;
                o_bb[lE + j] = f1 * bb + f2;
                o_pp[lE + j] = q2;
                o_da[lE + j] = rp;
                o_db[lE + j] = rr;
            }
        }
        __syncthreads();
        {
            float s = dot4_pf(*(float4(*)[4])&a[0], oin + halfB * (E / 2), lane);
            if (lane == 0) psum[wid] = s;
            barn(1 + (wid >> 1), 64);
            if (halfB == 0 && lane == 0)
                g_x[rowB] += psum[wid] + psum[wid + 1];
            if (actB2) {
                float s1 = dot4_pf(*(float4(*)[4])&a[4], oin + halfB * (E / 2), lane);
                if (lane == 0) psum[NWARP + wid] = s1;
                barn(1 + (wid >> 1), 64);
                if (halfB == 0 && lane == 0)
                    g_x[rowB + GWARPS / 2] += psum[NWARP + wid] + psum[NWARP + wid + 1];
            }
        }
        // prefetch phase-C rows gw (Fk) and gw+GWARPS (Fk, since <4096)
        pf8(p.Fk + lHE + (size_t)gw * E, lane, a);
        pf8(p.Fk + lHE + (size_t)(gw + GWARPS) * E, lane, b);
        grid_sync();

        // ========== Phase C: LN2 + mixes + Fk/Fr GEMVs (full rows) =========
        float* xn2 = sh; float* fxk = sh + E; float* fxr = sh + 2 * E;
        block_ln(g_x, p.ln2_w + lE, p.ln2_b + lE, xn2, red);
        for (int j = tid; j < E; j += NTHR) {
            float v = xn2[j], sxf = p.xx_ffn[lE + j];
            float ak = p.fmk[lE + j], br = p.fmr[lE + j];
            fxk[j] = v * ak + sxf * (1.f - ak);
            fxr[j] = v * br + sxf * (1.f - br);
            if (blockIdx.x == 0) o_xxf[lE + j] = v;
        }
        __syncthreads();
        {
            float s = dot8_pf(a, fxk, lane);
            s = fmaxf(s, 0.f);
            if (lane == 0) g_kf[gw] = s * s;
        }
        const bool actC3 = (gw < HID + E - 2 * GWARPS);   // gw < 1568
        const int  row3  = gw + 2 * GWARPS;
        if (actC3) {
            if (row3 < HID) pf8(p.Fk + lHE + (size_t)row3 * E, lane, a);
            else            pf8(p.Fr + lEE + (size_t)(row3 - HID) * E, lane, a);
        }
        {
            int row2 = gw + GWARPS;                        // always an Fk row
            float s = dot8_pf(b, fxk, lane);
            s = fmaxf(s, 0.f);
            if (lane == 0) g_kf[row2] = s * s;
        }
        if (actC3) {
            if (row3 < HID) {
                float s = dot8_pf(a, fxk, lane);
                s = fmaxf(s, 0.f);
                if (lane == 0) g_kf[row3] = s * s;
            } else {
                float s = dot8_pf(a, fxr, lane);
                if (lane == 0) g_rf[row3 - HID] = sigmoidf_(s);
            }
        }
        // prefetch phase-D quarter-rows (it0 + it1, all warps active)
        const int gD = gw >> 2, cD = gw & 3;
        const int DG = GWARPS / 4;                         // 444 groups
        pf8(p.Fv + lEH + (size_t)gD * HID + cD * (HID / 4), lane, a);
        pf8(p.Fv + lEH + (size_t)(gD + DG) * HID + cD * (HID / 4), lane, b);
        grid_sync();

        // ========== Phase D: Fv GEMV (quarter rows) + residual add =========
        {
            const float4* kf4 = (const float4*)g_kf;
            float4* sh4 = (float4*)sh;
            for (int j = tid; j < HID / 4; j += NTHR) sh4[j] = kf4[j];
        }
        __syncthreads();
        {
            const float* vq = sh + cD * (HID / 4);
            float s = dot8_pf(a, vq, lane);
            if (lane == 0) psd[wid] = s;
            const bool actD3 = (gD < E - 2 * (GWARPS / 4));   // gD < 136
            if (actD3)
                pf8(p.Fv + lEH + (size_t)(gD + 2 * DG) * HID + cD * (HID / 4), lane, a);
            barn(7 + (wid >> 2), 128);
            if (cD == 0 && lane == 0) {
                int base = wid;
                float s4 = psd[base] + psd[base + 1] + psd[base + 2] + psd[base + 3];
                g_x[gD] += g_rf[gD] * s4;
            }
            float s1 = dot8_pf(b, vq, lane);
            if (lane == 0) psd[NWARP + wid] = s1;
            barn(7 + (wid >> 2), 128);
            if (cD == 0 && lane == 0) {
                int base = wid;
                float s4 = psd[NWARP + base] + psd[NWARP + base + 1]
                         + psd[NWARP + base + 2] + psd[NWARP + base + 3];
                int r1 = gD + DG;
                g_x[r1] += g_rf[r1] * s4;
            }
            if (actD3) {
                float s2 = dot8_pf(a, vq, lane);
                if (lane == 0) psd[2 * NWARP + wid] = s2;
                barn(7 + (wid >> 2), 128);
                if (cD == 0 && lane == 0) {
                    int base = wid;
                    float s4 = psd[2 * NWARP + base] + psd[2 * NWARP + base + 1]
                             + psd[2 * NWARP + base + 2] + psd[2 * NWARP + base + 3];
                    int r2 = gD + 2 * DG;
                    g_x[r2] += g_rf[r2] * s4;
                }
            }
        }
        // prefetch next phase-A rows / head rows
        if (l + 1 < LAY) {
            pf8(wrowA(p, l + 1, gw), lane, a);
            if (actA2) pf8(wrowA(p, l + 1, gw + GWARPS), lane, b);
        } else {
            pf8(p.head_w + (size_t)gw * E, lane, a);
            pf8(p.head_w + (size_t)(gw + GWARPS) * E, lane, b);
        }
        grid_sync();
    }

    // ================= head: LN + [V,E] GEMV (ping-pong) ===================
    block_ln(g_x, p.lno_w, p.lno_b, sh, red);
    {
        int row = gw;       // a = row, b = row + GWARPS (both prefetched)
        while (true) {
            float s = dot8_pf(a, sh, lane);
            if (lane == 0) outv[row] = s;
            int rn = row + GWARPS;
            if (rn >= VOCAB) break;
            int rp = row + 2 * GWARPS;
            if (rp < VOCAB) pf8(p.head_w + (size_t)rp * E, lane, a);
            s = dot8_pf(b, sh, lane);
            if (lane == 0) outv[rn] = s;
            row = rp;
            if (row >= VOCAB) break;
            int rq = rn + 2 * GWARPS;
            if (rq < VOCAB) pf8(p.head_w + (size_t)rq * E, lane, b);
        }
    }
}

extern "C" void kernel_launch(void* const* d_in, const int* in_sizes, int n_in,
                              void* d_out, int out_size) {
    Params p;
    p.ctx    = (const int*)  d_in[0];
    p.xx_att = (const float*)d_in[1];
    p.aa_att = (const float*)d_in[2];
    p.bb_att = (const float*)d_in[3];
    p.pp_att = (const float*)d_in[4];
    p.xx_ffn = (const float*)d_in[5];
    p.emb_w  = (const float*)d_in[6];
    p.head_w = (const float*)d_in[7];
    p.ln0_w  = (const float*)d_in[8];
    p.ln0_b  = (const float*)d_in[9];
    p.ln1_w  = (const float*)d_in[10];
    p.ln1_b  = (const float*)d_in[11];
    p.ln2_w  = (const float*)d_in[12];
    p.ln2_b  = (const float*)d_in[13];
    p.lno_w  = (const float*)d_in[14];
    p.lno_b  = (const float*)d_in[15];
    p.mk     = (const float*)d_in[16];
    p.mv     = (const float*)d_in[17];
    p.mr     = (const float*)d_in[18];
    p.tf     = (const float*)d_in[19];
    p.td     = (const float*)d_in[20];
    p.Wr     = (const float*)d_in[21];
    p.Wk     = (const float*)d_in[22];
    p.Wv     = (const float*)d_in[23];
    p.Wo     = (const float*)d_in[24];
    p.fmk    = (const float*)d_in[25];
    p.fmr    = (const float*)d_in[26];
    p.Fr     = (const float*)d_in[27];
    p.Fk     = (const float*)d_in[28];
    p.Fv     = (const float*)d_in[29];
    p.out    = (float*)d_out;

    rwkv_kernel<<<NBLK, NTHR>>>(p);
}